// round 2
// baseline (speedup 1.0000x reference)
#include <cuda_runtime.h>
#include <cuda_bf16.h>
#include <math.h>

#define Bb 4
#define Cc 256
#define Tt 128
#define NBn 64
#define NFf 512

// ---------------- single scratch arena (device global; no allocation allowed) ----
// offsets in floats:
//   ln  : 0                        size  8M   (B*C*T*NB)
//   lh  : 8M                       size  8M
//   k   : 16M                      size  8M
//   v   : 24M                      size  8M
//   A   : 32M                      size 64M   (B*C*T*NF)
//   h2  : 96M                      size 128M  (B*2C*T*NF)
//   u   : 224M                     size 64M
//   qh  : 288M                     size 64M
//   hid : 352M                     size 64M
//   total 416M floats = 1.664 GB
#define SZ_SMALL (Bb * Cc * Tt * NBn)          // 8,388,608
#define SZ_BIG   (Bb * Cc * Tt * NFf)          // 67,108,864
__device__ float g_scratch[(size_t)4 * SZ_SMALL + (size_t)6 * SZ_BIG];

// ---------------- RMSNorm over channel dim ----------------
// x,y: [B,C,T,Wd]; one thread per (b,t,w) column
__global__ void rms_kernel(const float* __restrict__ x, const float* __restrict__ w,
                           float* __restrict__ y, int Wd, int total) {
    int idx = blockIdx.x * blockDim.x + threadIdx.x;
    if (idx >= total) return;
    int wcol = idx % Wd;
    int bt   = idx / Wd;
    int b = bt / Tt, t = bt % Tt;
    long base   = (long)b * Cc * Tt * Wd + (long)t * Wd + wcol;
    long stride = (long)Tt * Wd;
    float sum = 0.0f;
    #pragma unroll 8
    for (int c = 0; c < Cc; c++) {
        float v = x[base + (long)c * stride];
        sum += v * v;
    }
    float sc = rsqrtf(sum * (1.0f / Cc) + 1e-6f);
    #pragma unroll 8
    for (int c = 0; c < Cc; c++) {
        y[base + (long)c * stride] = x[base + (long)c * stride] * sc * w[c];
    }
}

// ---------------- generic fp32 GEMM: Y[b,m,n] = sum_k W[m,k] X[b,k,n] ----------------
// W: [M,K] row-major; X: per-batch [K,N]; Y: per-batch [M,N].
// epilogue: + bias[m]; act==1 -> SiLU; skip!=null -> += sscale * skip[b,m,n]
__global__ void __launch_bounds__(256) gemm_f32(
    const float* __restrict__ W, const float* __restrict__ X, float* __restrict__ Y,
    const float* __restrict__ bias, const float* __restrict__ skip,
    const float* __restrict__ sscale_p,
    int M, int K, int N, int act) {
    __shared__ float Ws[16][132];   // [k][m], padded
    __shared__ float Xs[16][128];   // [k][n]

    const int bb = blockIdx.z;
    const long bXoff = (long)bb * K * N;
    const long bYoff = (long)bb * M * N;
    const int m0 = blockIdx.y * 128;
    const int n0 = blockIdx.x * 128;
    const int tid = threadIdx.x;
    const int tx = tid & 15, ty = tid >> 4;

    const int wr = tid >> 2;          // 0..63
    const int wc = (tid & 3) << 2;    // 0,4,8,12
    const int xr = tid >> 5;          // 0..7
    const int xc = (tid & 31) << 2;   // 0..124

    const float* Wp0 = W + (long)(m0 + wr) * K + wc;
    const float* Wp1 = W + (long)(m0 + wr + 64) * K + wc;
    const float* Xp  = X + bXoff + (long)xr * N + n0 + xc;

    float4 w0 = *(const float4*)(Wp0);
    float4 w1 = *(const float4*)(Wp1);
    float4 x0 = *(const float4*)(Xp);
    float4 x1 = *(const float4*)(Xp + (long)8 * N);

    float acc[8][8];
    #pragma unroll
    for (int i = 0; i < 8; i++)
        #pragma unroll
        for (int j = 0; j < 8; j++) acc[i][j] = 0.0f;

    for (int k0 = 0; k0 < K; k0 += 16) {
        Ws[wc + 0][wr] = w0.x; Ws[wc + 1][wr] = w0.y;
        Ws[wc + 2][wr] = w0.z; Ws[wc + 3][wr] = w0.w;
        Ws[wc + 0][wr + 64] = w1.x; Ws[wc + 1][wr + 64] = w1.y;
        Ws[wc + 2][wr + 64] = w1.z; Ws[wc + 3][wr + 64] = w1.w;
        *(float4*)&Xs[xr][xc]     = x0;
        *(float4*)&Xs[xr + 8][xc] = x1;
        __syncthreads();
        if (k0 + 16 < K) {
            w0 = *(const float4*)(Wp0 + k0 + 16);
            w1 = *(const float4*)(Wp1 + k0 + 16);
            x0 = *(const float4*)(Xp + (long)(k0 + 16) * N);
            x1 = *(const float4*)(Xp + (long)(k0 + 24) * N);
        }
        #pragma unroll
        for (int kk = 0; kk < 16; kk++) {
            float4 a0 = *(float4*)&Ws[kk][ty * 8];
            float4 a1 = *(float4*)&Ws[kk][ty * 8 + 4];
            float4 b0 = *(float4*)&Xs[kk][tx * 8];
            float4 b1 = *(float4*)&Xs[kk][tx * 8 + 4];
            float av[8] = {a0.x, a0.y, a0.z, a0.w, a1.x, a1.y, a1.z, a1.w};
            float bv[8] = {b0.x, b0.y, b0.z, b0.w, b1.x, b1.y, b1.z, b1.w};
            #pragma unroll
            for (int i = 0; i < 8; i++)
                #pragma unroll
                for (int j = 0; j < 8; j++)
                    acc[i][j] += av[i] * bv[j];
        }
        __syncthreads();
    }

    float sc = 1.0f;
    if (sscale_p) sc = *sscale_p;

    #pragma unroll
    for (int i = 0; i < 8; i++) {
        int m = m0 + ty * 8 + i;
        float bi = bias ? bias[m] : 0.0f;
        long rowoff = bYoff + (long)m * N + n0 + tx * 8;
        float vv[8];
        #pragma unroll
        for (int j = 0; j < 8; j++) vv[j] = acc[i][j] + bi;
        if (act == 1) {
            #pragma unroll
            for (int j = 0; j < 8; j++) vv[j] = vv[j] / (1.0f + expf(-vv[j]));
        }
        if (skip) {
            float4 s0 = *(const float4*)&skip[rowoff];
            float4 s1 = *(const float4*)&skip[rowoff + 4];
            vv[0] += sc * s0.x; vv[1] += sc * s0.y; vv[2] += sc * s0.z; vv[3] += sc * s0.w;
            vv[4] += sc * s1.x; vv[5] += sc * s1.y; vv[6] += sc * s1.z; vv[7] += sc * s1.w;
        }
        float4 o0 = make_float4(vv[0], vv[1], vv[2], vv[3]);
        float4 o1 = make_float4(vv[4], vv[5], vv[6], vv[7]);
        *(float4*)&Y[rowoff]     = o0;
        *(float4*)&Y[rowoff + 4] = o1;
    }
}

// ---------------- SwiGLU: u = a * silu(g), h2 layout [B,2C,T,NF] ----------------
__global__ void swiglu_kernel(const float* __restrict__ h2, float* __restrict__ u) {
    const int QUARTER = Cc * Tt * NFf / 4;   // float4s per (batch, C-half)
    long i = (long)blockIdx.x * blockDim.x + threadIdx.x;   // float4 index over [B,C,T,NF]
    int bq = (int)(i / QUARTER);
    int r  = (int)(i % QUARTER);
    long a_idx = (long)bq * (2 * QUARTER) + r;
    float4 a = ((const float4*)h2)[a_idx];
    float4 g = ((const float4*)h2)[a_idx + QUARTER];
    float4 o;
    o.x = a.x * (g.x / (1.0f + expf(-g.x)));
    o.y = a.y * (g.y / (1.0f + expf(-g.y)));
    o.z = a.z * (g.z / (1.0f + expf(-g.z)));
    o.w = a.w * (g.w / (1.0f + expf(-g.w)));
    ((float4*)u)[i] = o;
}

// ---------------- fused attention per (b,t, f-tile of 128) ----------------
// q:[B,C,T,NF], k,v:[B,C,T,NB], eb:[NB,NF] bias transposed source, att:[B,C,T,NF]
__global__ void __launch_bounds__(256) attn_kernel(
    const float* __restrict__ q, const float* __restrict__ k, const float* __restrict__ v,
    const float* __restrict__ eb, const float* __restrict__ ssp, const float* __restrict__ psp,
    float* __restrict__ att) {
    __shared__ float sm[64 * 128 + 64 * 36];   // 41.98 KB
    float* wst = sm;              // phase2: weights^T [n][f] 64x128
    float* vs  = sm + 64 * 128;   // phase2: v [n][c+pad] 64x36
    float* qs  = sm;              // phase1: q [cc][f] 32x128
    float* ks  = sm + 32 * 128;   // phase1: k [cc][n] 32x64

    const int f0 = blockIdx.x * 128;
    const int t  = blockIdx.y;
    const int b  = blockIdx.z;
    const int tid = threadIdx.x;
    const long qbase = (long)b * Cc * Tt * NFf + (long)t * NFf;
    const long kbase = (long)b * Cc * Tt * NBn + (long)t * NBn;
    const float ss = *ssp, ps = *psp;
    const int tx = tid & 15, ty = tid >> 4;

    float s[8][4];
    #pragma unroll
    for (int i = 0; i < 8; i++)
        #pragma unroll
        for (int j = 0; j < 4; j++) s[i][j] = 0.0f;

    // phase 1: scores[f,n] = sum_c q[c,f] k[c,n]
    for (int c0 = 0; c0 < Cc; c0 += 32) {
        {
            const int fc = (tid & 31) << 2;
            const int cr = tid >> 5;
            #pragma unroll
            for (int r = 0; r < 4; r++) {
                int cc = cr + r * 8;
                *(float4*)&qs[cc * 128 + fc] =
                    *(const float4*)&q[qbase + (long)(c0 + cc) * Tt * NFf + f0 + fc];
            }
            const int nc  = (tid & 15) << 2;
            const int cr2 = tid >> 4;
            #pragma unroll
            for (int r = 0; r < 2; r++) {
                int cc = cr2 + r * 16;
                *(float4*)&ks[cc * 64 + nc] =
                    *(const float4*)&k[kbase + (long)(c0 + cc) * Tt * NBn + nc];
            }
        }
        __syncthreads();
        #pragma unroll 8
        for (int cc = 0; cc < 32; cc++) {
            float4 a0 = *(float4*)&qs[cc * 128 + ty * 8];
            float4 a1 = *(float4*)&qs[cc * 128 + ty * 8 + 4];
            float4 b4 = *(float4*)&ks[cc * 64 + tx * 4];
            float av[8] = {a0.x, a0.y, a0.z, a0.w, a1.x, a1.y, a1.z, a1.w};
            float bv[4] = {b4.x, b4.y, b4.z, b4.w};
            #pragma unroll
            for (int i = 0; i < 8; i++)
                #pragma unroll
                for (int j = 0; j < 4; j++)
                    s[i][j] += av[i] * bv[j];
        }
        __syncthreads();
    }

    // scale + bias + softmax over n (64 values spread over 16 lanes x 4)
    #pragma unroll
    for (int i = 0; i < 8; i++) {
        const int f = f0 + ty * 8 + i;
        float mx = -1e30f;
        #pragma unroll
        for (int j = 0; j < 4; j++) {
            s[i][j] = s[i][j] * ss + eb[(tx * 4 + j) * NFf + f] * ps;
            mx = fmaxf(mx, s[i][j]);
        }
        #pragma unroll
        for (int o = 8; o > 0; o >>= 1)
            mx = fmaxf(mx, __shfl_xor_sync(0xffffffffu, mx, o, 16));
        float sum = 0.0f;
        #pragma unroll
        for (int j = 0; j < 4; j++) {
            float e = expf(s[i][j] - mx);
            s[i][j] = e;
            sum += e;
        }
        #pragma unroll
        for (int o = 8; o > 0; o >>= 1)
            sum += __shfl_xor_sync(0xffffffffu, sum, o, 16);
        float inv = 1.0f / sum;
        #pragma unroll
        for (int j = 0; j < 4; j++) s[i][j] *= inv;
    }

    // store weights transposed [n][f] (qs/ks region is dead after last sync)
    #pragma unroll
    for (int i = 0; i < 8; i++)
        #pragma unroll
        for (int j = 0; j < 4; j++)
            wst[(tx * 4 + j) * 128 + ty * 8 + i] = s[i][j];

    // phase 2: att[c,f] = sum_n wst[n][f] * v[c,n]
    const int fx = tid & 15, cg = tid >> 4;
    for (int c0 = 0; c0 < Cc; c0 += 32) {
        {
            const int nc = (tid & 15) << 2;
            const int cr = tid >> 4;
            #pragma unroll
            for (int r = 0; r < 2; r++) {
                int cc = cr + r * 16;
                float4 vv4 = *(const float4*)&v[kbase + (long)(c0 + cc) * Tt * NBn + nc];
                vs[(nc + 0) * 36 + cc] = vv4.x;
                vs[(nc + 1) * 36 + cc] = vv4.y;
                vs[(nc + 2) * 36 + cc] = vv4.z;
                vs[(nc + 3) * 36 + cc] = vv4.w;
            }
        }
        __syncthreads();
        float a0[8], a1[8];
        #pragma unroll
        for (int jj = 0; jj < 8; jj++) { a0[jj] = 0.0f; a1[jj] = 0.0f; }
        #pragma unroll 16
        for (int n = 0; n < 64; n++) {
            float4 wa = *(float4*)&wst[n * 128 + fx * 8];
            float4 wb = *(float4*)&wst[n * 128 + fx * 8 + 4];
            float2 vv = *(float2*)&vs[n * 36 + cg * 2];
            float w8[8] = {wa.x, wa.y, wa.z, wa.w, wb.x, wb.y, wb.z, wb.w};
            #pragma unroll
            for (int jj = 0; jj < 8; jj++) {
                a0[jj] += vv.x * w8[jj];
                a1[jj] += vv.y * w8[jj];
            }
        }
        int c = c0 + cg * 2;
        long o0 = qbase + (long)c * Tt * NFf + f0 + fx * 8;
        long o1 = o0 + (long)Tt * NFf;
        *(float4*)&att[o0]     = make_float4(a0[0], a0[1], a0[2], a0[3]);
        *(float4*)&att[o0 + 4] = make_float4(a0[4], a0[5], a0[6], a0[7]);
        *(float4*)&att[o1]     = make_float4(a1[0], a1[1], a1[2], a1[3]);
        *(float4*)&att[o1 + 4] = make_float4(a1[4], a1[5], a1[6], a1[7]);
        __syncthreads();
    }
}

// ---------------- launch ----------------
extern "C" void kernel_launch(void* const* d_in, const int* in_sizes, int n_in,
                              void* d_out, int out_size) {
    (void)in_sizes; (void)n_in; (void)out_size;
    const float* latent = (const float*)d_in[0];
    const float* side   = (const float*)d_in[1];
    const float* eb     = (const float*)d_in[2];
    const float* lp_nw  = (const float*)d_in[3];
    const float* lp_w   = (const float*)d_in[4];
    const float* lp_b   = (const float*)d_in[5];
    const float* qn_w   = (const float*)d_in[6];
    const float* qin_w  = (const float*)d_in[7];
    const float* qin_b  = (const float*)d_in[8];
    const float* qout_w = (const float*)d_in[9];
    const float* qout_b = (const float*)d_in[10];
    const float* q_w    = (const float*)d_in[11];
    const float* q_b    = (const float*)d_in[12];
    const float* k_w    = (const float*)d_in[13];
    const float* k_b    = (const float*)d_in[14];
    const float* v_w    = (const float*)d_in[15];
    const float* v_b    = (const float*)d_in[16];
    const float* o_w    = (const float*)d_in[17];
    const float* o_b    = (const float*)d_in[18];
    const float* ffn_nw = (const float*)d_in[19];
    const float* fin_w  = (const float*)d_in[20];
    const float* fin_b  = (const float*)d_in[21];
    const float* fout_w = (const float*)d_in[22];
    const float* fout_b = (const float*)d_in[23];
    const float* ss     = (const float*)d_in[24];
    const float* ps     = (const float*)d_in[25];
    const float* qss    = (const float*)d_in[26];
    float* out = (float*)d_out;

    float* base = nullptr;
    cudaGetSymbolAddress((void**)&base, g_scratch);
    float* p_ln  = base;
    float* p_lh  = base + (size_t)1 * SZ_SMALL;
    float* p_k   = base + (size_t)2 * SZ_SMALL;
    float* p_v   = base + (size_t)3 * SZ_SMALL;
    float* p_A   = base + (size_t)4 * SZ_SMALL;
    float* p_h2  = p_A  + (size_t)1 * SZ_BIG;
    float* p_u   = p_h2 + (size_t)2 * SZ_BIG;
    float* p_qh  = p_u  + (size_t)1 * SZ_BIG;
    float* p_hid = p_qh + (size_t)1 * SZ_BIG;

    const int NTB = Tt * NBn;   // 8192
    const int NTF = Tt * NFf;   // 65536

    // latent path
    rms_kernel<<<(Bb * Tt * NBn) / 256, 256>>>(latent, lp_nw, p_ln, NBn, Bb * Tt * NBn);
    dim3 gNB(NTB / 128, 2, Bb);
    gemm_f32<<<gNB, 256>>>(lp_w, p_ln, p_lh, lp_b, nullptr, nullptr, Cc, Cc, NTB, 1);
    gemm_f32<<<gNB, 256>>>(k_w, p_lh, p_k, k_b, nullptr, nullptr, Cc, Cc, NTB, 0);
    gemm_f32<<<gNB, 256>>>(v_w, p_lh, p_v, v_b, nullptr, nullptr, Cc, Cc, NTB, 0);

    // query path
    rms_kernel<<<(Bb * Tt * NFf) / 256, 256>>>(side, qn_w, p_A, NFf, Bb * Tt * NFf);
    dim3 gIN(NTF / 128, 4, Bb);
    gemm_f32<<<gIN, 256>>>(qin_w, p_A, p_h2, qin_b, nullptr, nullptr, 2 * Cc, Cc, NTF, 0);
    swiglu_kernel<<<(Bb * Cc * Tt * NFf / 4) / 256, 256>>>(p_h2, p_u);
    dim3 gNF(NTF / 128, 2, Bb);
    gemm_f32<<<gNF, 256>>>(qout_w, p_u, p_qh, qout_b, nullptr, nullptr, Cc, Cc, NTF, 0);
    gemm_f32<<<gNF, 256>>>(q_w, p_qh, p_A, q_b, nullptr, nullptr, Cc, Cc, NTF, 0);

    // attention
    attn_kernel<<<dim3(NFf / 128, Tt, Bb), 256>>>(p_A, p_k, p_v, eb, ss, ps, p_u);

    // output proj + query skip
    gemm_f32<<<gNF, 256>>>(o_w, p_u, p_hid, o_b, p_qh, qss, Cc, Cc, NTF, 0);

    // FFN
    rms_kernel<<<(Bb * Tt * NFf) / 256, 256>>>(p_hid, ffn_nw, p_A, NFf, Bb * Tt * NFf);
    gemm_f32<<<gIN, 256>>>(fin_w, p_A, p_h2, fin_b, nullptr, nullptr, 2 * Cc, Cc, NTF, 0);
    swiglu_kernel<<<(Bb * Cc * Tt * NFf / 4) / 256, 256>>>(p_h2, p_u);
    gemm_f32<<<gNF, 256>>>(fout_w, p_u, out, fout_b, p_hid, nullptr, Cc, Cc, NTF, 0);
}

// round 4
// speedup vs baseline: 1.6033x; 1.6033x over previous
#include <cuda_runtime.h>
#include <cuda_bf16.h>
#include <math.h>

#define Bb 4
#define Cc 256
#define Tt 128
#define NBn 64
#define NFf 512

// ---------------- single scratch arena (device global; no allocation allowed) ----
// offsets in floats:
//   ln  : 0                        size  8M   (B*C*T*NB)
//   lh  : 8M                       size  8M
//   k   : 16M                      size  8M
//   v   : 24M                      size  8M
//   A   : 32M                      size 64M   (B*C*T*NF)
//   h2  : 96M                      size 128M  (B*2C*T*NF)
//   u   : 224M                     size 64M
//   qh  : 288M                     size 64M
//   hid : 352M                     size 64M
//   total 416M floats = 1.664 GB
#define SZ_SMALL (Bb * Cc * Tt * NBn)          // 8,388,608
#define SZ_BIG   (Bb * Cc * Tt * NFf)          // 67,108,864
__device__ float g_scratch[(size_t)4 * SZ_SMALL + (size_t)6 * SZ_BIG];

// ---------------- RMSNorm over channel dim ----------------
// x,y: [B,C,T,Wd]; one thread per (b,t,w) column
__global__ void rms_kernel(const float* __restrict__ x, const float* __restrict__ w,
                           float* __restrict__ y, int Wd, int total) {
    int idx = blockIdx.x * blockDim.x + threadIdx.x;
    if (idx >= total) return;
    int wcol = idx % Wd;
    int bt   = idx / Wd;
    int b = bt / Tt, t = bt % Tt;
    long base   = (long)b * Cc * Tt * Wd + (long)t * Wd + wcol;
    long stride = (long)Tt * Wd;
    float sum = 0.0f;
    #pragma unroll 8
    for (int c = 0; c < Cc; c++) {
        float v = x[base + (long)c * stride];
        sum += v * v;
    }
    float sc = rsqrtf(sum * (1.0f / Cc) + 1e-6f);
    #pragma unroll 8
    for (int c = 0; c < Cc; c++) {
        y[base + (long)c * stride] = x[base + (long)c * stride] * sc * w[c];
    }
}

// ---------------- generic fp32 GEMM: Y[b,m,n] = sum_k W[m,k] X[b,k,n] ----------------
// W: [M,K] row-major; X: per-batch [K,N]; Y: per-batch [M,N].
// epilogue: + bias[m]; act==1 -> SiLU; skip!=null -> += sscale * skip[b,m,n]
__global__ void __launch_bounds__(256) gemm_f32(
    const float* __restrict__ W, const float* __restrict__ X, float* __restrict__ Y,
    const float* __restrict__ bias, const float* __restrict__ skip,
    const float* __restrict__ sscale_p,
    int M, int K, int N, int act) {
    __shared__ float Ws[16][132];   // [k][m], padded
    __shared__ float Xs[16][128];   // [k][n]

    const int bb = blockIdx.z;
    const long bXoff = (long)bb * K * N;
    const long bYoff = (long)bb * M * N;
    const int m0 = blockIdx.y * 128;
    const int n0 = blockIdx.x * 128;
    const int tid = threadIdx.x;
    const int tx = tid & 15, ty = tid >> 4;

    const int wr = tid >> 2;          // 0..63
    const int wc = (tid & 3) << 2;    // 0,4,8,12
    const int xr = tid >> 5;          // 0..7
    const int xc = (tid & 31) << 2;   // 0..124

    const float* Wp0 = W + (long)(m0 + wr) * K + wc;
    const float* Wp1 = W + (long)(m0 + wr + 64) * K + wc;
    const float* Xp  = X + bXoff + (long)xr * N + n0 + xc;

    float4 w0 = *(const float4*)(Wp0);
    float4 w1 = *(const float4*)(Wp1);
    float4 x0 = *(const float4*)(Xp);
    float4 x1 = *(const float4*)(Xp + (long)8 * N);

    float acc[8][8];
    #pragma unroll
    for (int i = 0; i < 8; i++)
        #pragma unroll
        for (int j = 0; j < 8; j++) acc[i][j] = 0.0f;

    for (int k0 = 0; k0 < K; k0 += 16) {
        Ws[wc + 0][wr] = w0.x; Ws[wc + 1][wr] = w0.y;
        Ws[wc + 2][wr] = w0.z; Ws[wc + 3][wr] = w0.w;
        Ws[wc + 0][wr + 64] = w1.x; Ws[wc + 1][wr + 64] = w1.y;
        Ws[wc + 2][wr + 64] = w1.z; Ws[wc + 3][wr + 64] = w1.w;
        *(float4*)&Xs[xr][xc]     = x0;
        *(float4*)&Xs[xr + 8][xc] = x1;
        __syncthreads();
        if (k0 + 16 < K) {
            w0 = *(const float4*)(Wp0 + k0 + 16);
            w1 = *(const float4*)(Wp1 + k0 + 16);
            x0 = *(const float4*)(Xp + (long)(k0 + 16) * N);
            x1 = *(const float4*)(Xp + (long)(k0 + 24) * N);
        }
        #pragma unroll
        for (int kk = 0; kk < 16; kk++) {
            float4 a0 = *(float4*)&Ws[kk][ty * 8];
            float4 a1 = *(float4*)&Ws[kk][ty * 8 + 4];
            float4 b0 = *(float4*)&Xs[kk][tx * 8];
            float4 b1 = *(float4*)&Xs[kk][tx * 8 + 4];
            float av[8] = {a0.x, a0.y, a0.z, a0.w, a1.x, a1.y, a1.z, a1.w};
            float bv[8] = {b0.x, b0.y, b0.z, b0.w, b1.x, b1.y, b1.z, b1.w};
            #pragma unroll
            for (int i = 0; i < 8; i++)
                #pragma unroll
                for (int j = 0; j < 8; j++)
                    acc[i][j] += av[i] * bv[j];
        }
        __syncthreads();
    }

    float sc = 1.0f;
    if (sscale_p) sc = *sscale_p;

    #pragma unroll
    for (int i = 0; i < 8; i++) {
        int m = m0 + ty * 8 + i;
        float bi = bias ? bias[m] : 0.0f;
        long rowoff = bYoff + (long)m * N + n0 + tx * 8;
        float vv[8];
        #pragma unroll
        for (int j = 0; j < 8; j++) vv[j] = acc[i][j] + bi;
        if (act == 1) {
            #pragma unroll
            for (int j = 0; j < 8; j++) vv[j] = vv[j] / (1.0f + expf(-vv[j]));
        }
        if (skip) {
            float4 s0 = *(const float4*)&skip[rowoff];
            float4 s1 = *(const float4*)&skip[rowoff + 4];
            vv[0] += sc * s0.x; vv[1] += sc * s0.y; vv[2] += sc * s0.z; vv[3] += sc * s0.w;
            vv[4] += sc * s1.x; vv[5] += sc * s1.y; vv[6] += sc * s1.z; vv[7] += sc * s1.w;
        }
        float4 o0 = make_float4(vv[0], vv[1], vv[2], vv[3]);
        float4 o1 = make_float4(vv[4], vv[5], vv[6], vv[7]);
        *(float4*)&Y[rowoff]     = o0;
        *(float4*)&Y[rowoff + 4] = o1;
    }
}

// ---------------- SwiGLU: u = a * silu(g), h2 layout [B,2C,T,NF] ----------------
__global__ void swiglu_kernel(const float* __restrict__ h2, float* __restrict__ u) {
    const int QUARTER = Cc * Tt * NFf / 4;   // float4s per (batch, C-half)
    long i = (long)blockIdx.x * blockDim.x + threadIdx.x;   // float4 index over [B,C,T,NF]
    int bq = (int)(i / QUARTER);
    int r  = (int)(i % QUARTER);
    long a_idx = (long)bq * (2 * QUARTER) + r;
    float4 a = ((const float4*)h2)[a_idx];
    float4 g = ((const float4*)h2)[a_idx + QUARTER];
    float4 o;
    o.x = a.x * (g.x / (1.0f + expf(-g.x)));
    o.y = a.y * (g.y / (1.0f + expf(-g.y)));
    o.z = a.z * (g.z / (1.0f + expf(-g.z)));
    o.w = a.w * (g.w / (1.0f + expf(-g.w)));
    ((float4*)u)[i] = o;
}

// ---------------- fused attention per (b,t, f-tile of 128) ----------------
// q:[B,C,T,NF], k,v:[B,C,T,NB], eb:[NB,NF] bias transposed source, att:[B,C,T,NF]
__global__ void __launch_bounds__(256) attn_kernel(
    const float* __restrict__ q, const float* __restrict__ k, const float* __restrict__ v,
    const float* __restrict__ eb, const float* __restrict__ ssp, const float* __restrict__ psp,
    float* __restrict__ att) {
    __shared__ float sm[64 * 128 + 64 * 36];   // 41.98 KB
    float* wst = sm;              // phase2: weights^T [n][f] 64x128
    float* vs  = sm + 64 * 128;   // phase2: v [n][c+pad] 64x36
    float* qs  = sm;              // phase1: q [cc][f] 32x128
    float* ks  = sm + 32 * 128;   // phase1: k [cc][n] 32x64

    const int f0 = blockIdx.x * 128;
    const int t  = blockIdx.y;
    const int b  = blockIdx.z;
    const int tid = threadIdx.x;
    const long qbase = (long)b * Cc * Tt * NFf + (long)t * NFf;
    const long kbase = (long)b * Cc * Tt * NBn + (long)t * NBn;
    const float ss = *ssp, ps = *psp;
    const int tx = tid & 15, ty = tid >> 4;

    float s[8][4];
    #pragma unroll
    for (int i = 0; i < 8; i++)
        #pragma unroll
        for (int j = 0; j < 4; j++) s[i][j] = 0.0f;

    // phase 1: scores[f,n] = sum_c q[c,f] k[c,n]
    for (int c0 = 0; c0 < Cc; c0 += 32) {
        {
            const int fc = (tid & 31) << 2;
            const int cr = tid >> 5;
            #pragma unroll
            for (int r = 0; r < 4; r++) {
                int cc = cr + r * 8;
                *(float4*)&qs[cc * 128 + fc] =
                    *(const float4*)&q[qbase + (long)(c0 + cc) * Tt * NFf + f0 + fc];
            }
            const int nc  = (tid & 15) << 2;
            const int cr2 = tid >> 4;
            #pragma unroll
            for (int r = 0; r < 2; r++) {
                int cc = cr2 + r * 16;
                *(float4*)&ks[cc * 64 + nc] =
                    *(const float4*)&k[kbase + (long)(c0 + cc) * Tt * NBn + nc];
            }
        }
        __syncthreads();
        #pragma unroll 8
        for (int cc = 0; cc < 32; cc++) {
            float4 a0 = *(float4*)&qs[cc * 128 + ty * 8];
            float4 a1 = *(float4*)&qs[cc * 128 + ty * 8 + 4];
            float4 b4 = *(float4*)&ks[cc * 64 + tx * 4];
            float av[8] = {a0.x, a0.y, a0.z, a0.w, a1.x, a1.y, a1.z, a1.w};
            float bv[4] = {b4.x, b4.y, b4.z, b4.w};
            #pragma unroll
            for (int i = 0; i < 8; i++)
                #pragma unroll
                for (int j = 0; j < 4; j++)
                    s[i][j] += av[i] * bv[j];
        }
        __syncthreads();
    }

    // scale + bias + softmax over n (64 values spread over 16 lanes x 4)
    #pragma unroll
    for (int i = 0; i < 8; i++) {
        const int f = f0 + ty * 8 + i;
        float mx = -1e30f;
        #pragma unroll
        for (int j = 0; j < 4; j++) {
            s[i][j] = s[i][j] * ss + eb[(tx * 4 + j) * NFf + f] * ps;
            mx = fmaxf(mx, s[i][j]);
        }
        #pragma unroll
        for (int o = 8; o > 0; o >>= 1)
            mx = fmaxf(mx, __shfl_xor_sync(0xffffffffu, mx, o, 16));
        float sum = 0.0f;
        #pragma unroll
        for (int j = 0; j < 4; j++) {
            float e = expf(s[i][j] - mx);
            s[i][j] = e;
            sum += e;
        }
        #pragma unroll
        for (int o = 8; o > 0; o >>= 1)
            sum += __shfl_xor_sync(0xffffffffu, sum, o, 16);
        float inv = 1.0f / sum;
        #pragma unroll
        for (int j = 0; j < 4; j++) s[i][j] *= inv;
    }

    // store weights transposed [n][f] (qs/ks region is dead after last sync)
    #pragma unroll
    for (int i = 0; i < 8; i++)
        #pragma unroll
        for (int j = 0; j < 4; j++)
            wst[(tx * 4 + j) * 128 + ty * 8 + i] = s[i][j];

    // phase 2: att[c,f] = sum_n wst[n][f] * v[c,n]
    const int fx = tid & 15, cg = tid >> 4;
    for (int c0 = 0; c0 < Cc; c0 += 32) {
        {
            const int nc = (tid & 15) << 2;
            const int cr = tid >> 4;
            #pragma unroll
            for (int r = 0; r < 2; r++) {
                int cc = cr + r * 16;
                float4 vv4 = *(const float4*)&v[kbase + (long)(c0 + cc) * Tt * NBn + nc];
                vs[(nc + 0) * 36 + cc] = vv4.x;
                vs[(nc + 1) * 36 + cc] = vv4.y;
                vs[(nc + 2) * 36 + cc] = vv4.z;
                vs[(nc + 3) * 36 + cc] = vv4.w;
            }
        }
        __syncthreads();
        float a0[8], a1[8];
        #pragma unroll
        for (int jj = 0; jj < 8; jj++) { a0[jj] = 0.0f; a1[jj] = 0.0f; }
        #pragma unroll 16
        for (int n = 0; n < 64; n++) {
            float4 wa = *(float4*)&wst[n * 128 + fx * 8];
            float4 wb = *(float4*)&wst[n * 128 + fx * 8 + 4];
            float2 vv = *(float2*)&vs[n * 36 + cg * 2];
            float w8[8] = {wa.x, wa.y, wa.z, wa.w, wb.x, wb.y, wb.z, wb.w};
            #pragma unroll
            for (int jj = 0; jj < 8; jj++) {
                a0[jj] += vv.x * w8[jj];
                a1[jj] += vv.y * w8[jj];
            }
        }
        int c = c0 + cg * 2;
        long o0 = qbase + (long)c * Tt * NFf + f0 + fx * 8;
        long o1 = o0 + (long)Tt * NFf;
        *(float4*)&att[o0]     = make_float4(a0[0], a0[1], a0[2], a0[3]);
        *(float4*)&att[o0 + 4] = make_float4(a0[4], a0[5], a0[6], a0[7]);
        *(float4*)&att[o1]     = make_float4(a1[0], a1[1], a1[2], a1[3]);
        *(float4*)&att[o1 + 4] = make_float4(a1[4], a1[5], a1[6], a1[7]);
        __syncthreads();
    }
}

// ---------------- launch ----------------
extern "C" void kernel_launch(void* const* d_in, const int* in_sizes, int n_in,
                              void* d_out, int out_size) {
    (void)in_sizes; (void)n_in; (void)out_size;
    const float* latent = (const float*)d_in[0];
    const float* side   = (const float*)d_in[1];
    const float* eb     = (const float*)d_in[2];
    const float* lp_nw  = (const float*)d_in[3];
    const float* lp_w   = (const float*)d_in[4];
    const float* lp_b   = (const float*)d_in[5];
    const float* qn_w   = (const float*)d_in[6];
    const float* qin_w  = (const float*)d_in[7];
    const float* qin_b  = (const float*)d_in[8];
    const float* qout_w = (const float*)d_in[9];
    const float* qout_b = (const float*)d_in[10];
    const float* q_w    = (const float*)d_in[11];
    const float* q_b    = (const float*)d_in[12];
    const float* k_w    = (const float*)d_in[13];
    const float* k_b    = (const float*)d_in[14];
    const float* v_w    = (const float*)d_in[15];
    const float* v_b    = (const float*)d_in[16];
    const float* o_w    = (const float*)d_in[17];
    const float* o_b    = (const float*)d_in[18];
    const float* ffn_nw = (const float*)d_in[19];
    const float* fin_w  = (const float*)d_in[20];
    const float* fin_b  = (const float*)d_in[21];
    const float* fout_w = (const float*)d_in[22];
    const float* fout_b = (const float*)d_in[23];
    const float* ss     = (const float*)d_in[24];
    const float* ps     = (const float*)d_in[25];
    const float* qss    = (const float*)d_in[26];
    float* out = (float*)d_out;

    float* base = nullptr;
    cudaGetSymbolAddress((void**)&base, g_scratch);
    float* p_ln  = base;
    float* p_lh  = base + (size_t)1 * SZ_SMALL;
    float* p_k   = base + (size_t)2 * SZ_SMALL;
    float* p_v   = base + (size_t)3 * SZ_SMALL;
    float* p_A   = base + (size_t)4 * SZ_SMALL;
    float* p_h2  = p_A  + (size_t)1 * SZ_BIG;
    float* p_u   = p_h2 + (size_t)2 * SZ_BIG;
    float* p_qh  = p_u  + (size_t)1 * SZ_BIG;
    float* p_hid = p_qh + (size_t)1 * SZ_BIG;

    const int NTB = Tt * NBn;   // 8192
    const int NTF = Tt * NFf;   // 65536

    // latent path
    rms_kernel<<<(Bb * Tt * NBn) / 256, 256>>>(latent, lp_nw, p_ln, NBn, Bb * Tt * NBn);
    dim3 gNB(NTB / 128, 2, Bb);
    gemm_f32<<<gNB, 256>>>(lp_w, p_ln, p_lh, lp_b, nullptr, nullptr, Cc, Cc, NTB, 1);
    gemm_f32<<<gNB, 256>>>(k_w, p_lh, p_k, k_b, nullptr, nullptr, Cc, Cc, NTB, 0);
    gemm_f32<<<gNB, 256>>>(v_w, p_lh, p_v, v_b, nullptr, nullptr, Cc, Cc, NTB, 0);

    // query path
    rms_kernel<<<(Bb * Tt * NFf) / 256, 256>>>(side, qn_w, p_A, NFf, Bb * Tt * NFf);
    dim3 gIN(NTF / 128, 4, Bb);
    gemm_f32<<<gIN, 256>>>(qin_w, p_A, p_h2, qin_b, nullptr, nullptr, 2 * Cc, Cc, NTF, 0);
    swiglu_kernel<<<(Bb * Cc * Tt * NFf / 4) / 256, 256>>>(p_h2, p_u);
    dim3 gNF(NTF / 128, 2, Bb);
    gemm_f32<<<gNF, 256>>>(qout_w, p_u, p_qh, qout_b, nullptr, nullptr, Cc, Cc, NTF, 0);
    gemm_f32<<<gNF, 256>>>(q_w, p_qh, p_A, q_b, nullptr, nullptr, Cc, Cc, NTF, 0);

    // attention
    attn_kernel<<<dim3(NFf / 128, Tt, Bb), 256>>>(p_A, p_k, p_v, eb, ss, ps, p_u);

    // output proj + query skip
    gemm_f32<<<gNF, 256>>>(o_w, p_u, p_hid, o_b, p_qh, qss, Cc, Cc, NTF, 0);

    // FFN
    rms_kernel<<<(Bb * Tt * NFf) / 256, 256>>>(p_hid, ffn_nw, p_A, NFf, Bb * Tt * NFf);
    gemm_f32<<<gIN, 256>>>(fin_w, p_A, p_h2, fin_b, nullptr, nullptr, 2 * Cc, Cc, NTF, 0);
    swiglu_kernel<<<(Bb * Cc * Tt * NFf / 4) / 256, 256>>>(p_h2, p_u);
    gemm_f32<<<gNF, 256>>>(fout_w, p_u, out, fout_b, p_hid, nullptr, Cc, Cc, NTF, 0);
}

// round 6
// speedup vs baseline: 2.0923x; 1.3050x over previous
#include <cuda_runtime.h>
#include <cuda_bf16.h>
#include <math.h>
#include <stdint.h>

#define Bb 4
#define Cc 256
#define Tt 128
#define NBn 64
#define NFf 512

#define SZ_SMALL (Bb * Cc * Tt * NBn)
#define SZ_BIG   (Bb * Cc * Tt * NFf)
__device__ float g_scratch[(size_t)4 * SZ_SMALL + (size_t)6 * SZ_BIG];

__device__ __forceinline__ uint32_t smem_u32(const void* p) {
    uint32_t a;
    asm("{ .reg .u64 t; cvta.to.shared.u64 t, %1; cvt.u32.u64 %0, t; }" : "=r"(a) : "l"(p));
    return a;
}
#define SWZ128(x) ((x) ^ (((x) >> 3) & 0x70))

__device__ __forceinline__ void split8(float4 a, float4 b, uint32_t* h, uint32_t* l) {
    __nv_bfloat162 h0 = __floats2bfloat162_rn(a.x, a.y);
    __nv_bfloat162 h1 = __floats2bfloat162_rn(a.z, a.w);
    __nv_bfloat162 h2 = __floats2bfloat162_rn(b.x, b.y);
    __nv_bfloat162 h3 = __floats2bfloat162_rn(b.z, b.w);
    float2 f0 = __bfloat1622float2(h0), f1 = __bfloat1622float2(h1);
    float2 f2 = __bfloat1622float2(h2), f3 = __bfloat1622float2(h3);
    __nv_bfloat162 l0 = __floats2bfloat162_rn(a.x - f0.x, a.y - f0.y);
    __nv_bfloat162 l1 = __floats2bfloat162_rn(a.z - f1.x, a.w - f1.y);
    __nv_bfloat162 l2 = __floats2bfloat162_rn(b.x - f2.x, b.y - f2.y);
    __nv_bfloat162 l3 = __floats2bfloat162_rn(b.z - f3.x, b.w - f3.y);
    h[0] = *(uint32_t*)&h0; h[1] = *(uint32_t*)&h1; h[2] = *(uint32_t*)&h2; h[3] = *(uint32_t*)&h3;
    l[0] = *(uint32_t*)&l0; l[1] = *(uint32_t*)&l1; l[2] = *(uint32_t*)&l2; l[3] = *(uint32_t*)&l3;
}

#define LDM_X4(r0, r1, r2, r3, a) \
    asm volatile("ldmatrix.sync.aligned.m8n8.x4.shared.b16 {%0,%1,%2,%3}, [%4];" \
        : "=r"(r0), "=r"(r1), "=r"(r2), "=r"(r3) : "r"(a))
#define MMA_BF16(c, a, b0, b1) \
    asm volatile("mma.sync.aligned.m16n8k16.row.col.f32.bf16.bf16.f32 " \
        "{%0,%1,%2,%3}, {%4,%5,%6,%7}, {%8,%9}, {%0,%1,%2,%3};" \
        : "+f"((c)[0]), "+f"((c)[1]), "+f"((c)[2]), "+f"((c)[3]) \
        : "r"((a)[0]), "r"((a)[1]), "r"((a)[2]), "r"((a)[3]), "r"(b0), "r"(b1))

// ===== HMMA GEMM: Y[b,m,n] = sum_k W[m,k] X[b,k,n], K=256, bf16-split x3 =====
// 512 thr, tile 128m x 128n, Kc=64, smem 64KB (Ah|Al|Bh|Bl 16KB each), reg prefetch.
__global__ void __launch_bounds__(512) gemm_mma(
    const float* __restrict__ W, const float* __restrict__ X, float* __restrict__ Y,
    const float* __restrict__ bias, const float* __restrict__ skip,
    const float* __restrict__ sscale_p, int Mout, int N, int act) {
    extern __shared__ char smem[];
    const uint32_t sb = smem_u32(smem);
    const int tid = threadIdx.x, wid = tid >> 5, lane = tid & 31;
    const long bXoff = (long)blockIdx.z * 256 * N;
    const long bYoff = (long)blockIdx.z * Mout * N;
    const int n0 = blockIdx.x * 128;
    const int m0 = blockIdx.y * 128;

    const int ag = tid & 7, ar = tid >> 3;          // A staging: k-grp, row
    const int bkg = wid & 7, bnh = wid >> 3;        // B staging: k-grp, n-half

    float aP[16], bP[16];
    // prefetch chunk 0
    {
        #pragma unroll
        for (int it = 0; it < 2; it++) {
            const float* s = W + (long)(m0 + ar + it * 64) * 256 + ag * 8;
            float4 u0 = *(const float4*)s, u1 = *(const float4*)(s + 4);
            aP[it*8+0]=u0.x; aP[it*8+1]=u0.y; aP[it*8+2]=u0.z; aP[it*8+3]=u0.w;
            aP[it*8+4]=u1.x; aP[it*8+5]=u1.y; aP[it*8+6]=u1.z; aP[it*8+7]=u1.w;
        }
        #pragma unroll
        for (int it = 0; it < 2; it++) {
            int n = lane + bnh * 32 + it * 64;
            const float* s = X + bXoff + (long)(bkg * 8) * N + n0 + n;
            #pragma unroll
            for (int j = 0; j < 8; j++) bP[it*8+j] = s[(long)j * N];
        }
    }

    const int wm = wid & 3, wn = wid >> 2;          // warp: 4 m-grps x 4 n-grps (32x32)
    float acc[2][4][4];
    #pragma unroll
    for (int mi = 0; mi < 2; mi++)
        #pragma unroll
        for (int ni = 0; ni < 4; ni++)
            #pragma unroll
            for (int r = 0; r < 4; r++) acc[mi][ni][r] = 0.0f;

    // ldmatrix per-lane address precompute
    uint32_t aRow[2], aMask[2];
    #pragma unroll
    for (int mi = 0; mi < 2; mi++) {
        uint32_t row = wm * 32 + mi * 16 + (lane & 15);
        aRow[mi] = row * 128; aMask[mi] = (aRow[mi] >> 3) & 0x70;
    }
    const uint32_t aKH = (lane >> 4) * 16;
    uint32_t bRow[2], bMask[2];
    #pragma unroll
    for (int pr = 0; pr < 2; pr++) {
        uint32_t nr = wn * 32 + pr * 16 + (lane >> 4) * 8 + (lane & 7);
        bRow[pr] = nr * 128; bMask[pr] = (bRow[pr] >> 3) & 0x70;
    }
    const uint32_t bKH = ((lane >> 3) & 1) * 16;

    for (int ch = 0; ch < 4; ch++) {
        // store staged regs -> smem (split hi/lo)
        #pragma unroll
        for (int it = 0; it < 2; it++) {
            float4 u0 = make_float4(aP[it*8+0], aP[it*8+1], aP[it*8+2], aP[it*8+3]);
            float4 u1 = make_float4(aP[it*8+4], aP[it*8+5], aP[it*8+6], aP[it*8+7]);
            uint32_t h[4], l[4];
            split8(u0, u1, h, l);
            uint32_t off = SWZ128((uint32_t)((ar + it * 64) * 128 + ag * 16));
            asm volatile("st.shared.v4.b32 [%0], {%1,%2,%3,%4};" :: "r"(sb + off), "r"(h[0]), "r"(h[1]), "r"(h[2]), "r"(h[3]) : "memory");
            asm volatile("st.shared.v4.b32 [%0], {%1,%2,%3,%4};" :: "r"(sb + 16384 + off), "r"(l[0]), "r"(l[1]), "r"(l[2]), "r"(l[3]) : "memory");
        }
        #pragma unroll
        for (int it = 0; it < 2; it++) {
            int n = lane + bnh * 32 + it * 64;
            float4 u0 = make_float4(bP[it*8+0], bP[it*8+1], bP[it*8+2], bP[it*8+3]);
            float4 u1 = make_float4(bP[it*8+4], bP[it*8+5], bP[it*8+6], bP[it*8+7]);
            uint32_t h[4], l[4];
            split8(u0, u1, h, l);
            uint32_t off = SWZ128((uint32_t)(n * 128 + bkg * 16));
            asm volatile("st.shared.v4.b32 [%0], {%1,%2,%3,%4};" :: "r"(sb + 32768 + off), "r"(h[0]), "r"(h[1]), "r"(h[2]), "r"(h[3]) : "memory");
            asm volatile("st.shared.v4.b32 [%0], {%1,%2,%3,%4};" :: "r"(sb + 49152 + off), "r"(l[0]), "r"(l[1]), "r"(l[2]), "r"(l[3]) : "memory");
        }
        __syncthreads();
        // prefetch next chunk (retires during compute)
        if (ch < 3) {
            #pragma unroll
            for (int it = 0; it < 2; it++) {
                const float* s = W + (long)(m0 + ar + it * 64) * 256 + (ch + 1) * 64 + ag * 8;
                float4 u0 = *(const float4*)s, u1 = *(const float4*)(s + 4);
                aP[it*8+0]=u0.x; aP[it*8+1]=u0.y; aP[it*8+2]=u0.z; aP[it*8+3]=u0.w;
                aP[it*8+4]=u1.x; aP[it*8+5]=u1.y; aP[it*8+6]=u1.z; aP[it*8+7]=u1.w;
            }
            #pragma unroll
            for (int it = 0; it < 2; it++) {
                int n = lane + bnh * 32 + it * 64;
                const float* s = X + bXoff + (long)((ch + 1) * 64 + bkg * 8) * N + n0 + n;
                #pragma unroll
                for (int j = 0; j < 8; j++) bP[it*8+j] = s[(long)j * N];
            }
        }
        // 3 passes: (Ah,Bh) (Ah,Bl) (Al,Bh)
        const uint32_t aoff[3] = {0u, 0u, 16384u};
        const uint32_t boff[3] = {32768u, 49152u, 32768u};
        #pragma unroll
        for (int p = 0; p < 3; p++) {
            const uint32_t Ab = sb + aoff[p], Bbs = sb + boff[p];
            #pragma unroll
            for (int kk = 0; kk < 4; kk++) {
                uint32_t af[2][4], bf[4][2];
                #pragma unroll
                for (int mi = 0; mi < 2; mi++) {
                    uint32_t addr = Ab + aRow[mi] + (((uint32_t)(kk * 32) + aKH) ^ aMask[mi]);
                    LDM_X4(af[mi][0], af[mi][1], af[mi][2], af[mi][3], addr);
                }
                #pragma unroll
                for (int pr = 0; pr < 2; pr++) {
                    uint32_t addr = Bbs + bRow[pr] + (((uint32_t)(kk * 32) + bKH) ^ bMask[pr]);
                    LDM_X4(bf[pr*2][0], bf[pr*2][1], bf[pr*2+1][0], bf[pr*2+1][1], addr);
                }
                #pragma unroll
                for (int mi = 0; mi < 2; mi++)
                    #pragma unroll
                    for (int ni = 0; ni < 4; ni++)
                        MMA_BF16(acc[mi][ni], af[mi], bf[ni][0], bf[ni][1]);
            }
        }
        __syncthreads();
    }

    // epilogue
    const int gid = lane >> 2, tig = lane & 3;
    const float sc = sscale_p ? *sscale_p : 1.0f;
    #pragma unroll
    for (int mi = 0; mi < 2; mi++) {
        #pragma unroll
        for (int ni = 0; ni < 4; ni++) {
            int m1 = m0 + wm * 32 + mi * 16 + gid;
            int n  = n0 + wn * 32 + ni * 8 + tig * 2;
            float v0 = acc[mi][ni][0] + bias[m1];
            float v1 = acc[mi][ni][1] + bias[m1];
            float v2 = acc[mi][ni][2] + bias[m1 + 8];
            float v3 = acc[mi][ni][3] + bias[m1 + 8];
            if (act) {
                v0 = v0 / (1.0f + expf(-v0)); v1 = v1 / (1.0f + expf(-v1));
                v2 = v2 / (1.0f + expf(-v2)); v3 = v3 / (1.0f + expf(-v3));
            }
            long o1 = bYoff + (long)m1 * N + n;
            long o2 = o1 + (long)8 * N;
            if (skip) {
                float2 s1 = *(const float2*)&skip[o1];
                float2 s2 = *(const float2*)&skip[o2];
                v0 += sc * s1.x; v1 += sc * s1.y; v2 += sc * s2.x; v3 += sc * s2.y;
            }
            *(float2*)&Y[o1] = make_float2(v0, v1);
            *(float2*)&Y[o2] = make_float2(v2, v3);
        }
    }
}

// ---------------- RMSNorm (unchanged, passing) ----------------
__global__ void rms_kernel(const float* __restrict__ x, const float* __restrict__ w,
                           float* __restrict__ y, int Wd, int total) {
    int idx = blockIdx.x * blockDim.x + threadIdx.x;
    if (idx >= total) return;
    int wcol = idx % Wd;
    int bt   = idx / Wd;
    int b = bt / Tt, t = bt % Tt;
    long base   = (long)b * Cc * Tt * Wd + (long)t * Wd + wcol;
    long stride = (long)Tt * Wd;
    float sum = 0.0f;
    #pragma unroll 8
    for (int c = 0; c < Cc; c++) {
        float v = x[base + (long)c * stride];
        sum += v * v;
    }
    float sc = rsqrtf(sum * (1.0f / Cc) + 1e-6f);
    #pragma unroll 8
    for (int c = 0; c < Cc; c++)
        y[base + (long)c * stride] = x[base + (long)c * stride] * sc * w[c];
}

// ---------------- SwiGLU (unchanged, passing) ----------------
__global__ void swiglu_kernel(const float* __restrict__ h2, float* __restrict__ u) {
    const int QUARTER = Cc * Tt * NFf / 4;
    long i = (long)blockIdx.x * blockDim.x + threadIdx.x;
    int bq = (int)(i / QUARTER);
    int r  = (int)(i % QUARTER);
    long a_idx = (long)bq * (2 * QUARTER) + r;
    float4 a = ((const float4*)h2)[a_idx];
    float4 g = ((const float4*)h2)[a_idx + QUARTER];
    float4 o;
    o.x = a.x * (g.x / (1.0f + expf(-g.x)));
    o.y = a.y * (g.y / (1.0f + expf(-g.y)));
    o.z = a.z * (g.z / (1.0f + expf(-g.z)));
    o.w = a.w * (g.w / (1.0f + expf(-g.w)));
    ((float4*)u)[i] = o;
}

// ---------------- fused attention (unchanged, passing) ----------------
__global__ void __launch_bounds__(256) attn_kernel(
    const float* __restrict__ q, const float* __restrict__ k, const float* __restrict__ v,
    const float* __restrict__ eb, const float* __restrict__ ssp, const float* __restrict__ psp,
    float* __restrict__ att) {
    __shared__ float sm[64 * 128 + 64 * 36];
    float* wst = sm;
    float* vs  = sm + 64 * 128;
    float* qs  = sm;
    float* ks  = sm + 32 * 128;

    const int f0 = blockIdx.x * 128;
    const int t  = blockIdx.y;
    const int b  = blockIdx.z;
    const int tid = threadIdx.x;
    const long qbase = (long)b * Cc * Tt * NFf + (long)t * NFf;
    const long kbase = (long)b * Cc * Tt * NBn + (long)t * NBn;
    const float ss = *ssp, ps = *psp;
    const int tx = tid & 15, ty = tid >> 4;

    float s[8][4];
    #pragma unroll
    for (int i = 0; i < 8; i++)
        #pragma unroll
        for (int j = 0; j < 4; j++) s[i][j] = 0.0f;

    for (int c0 = 0; c0 < Cc; c0 += 32) {
        {
            const int fc = (tid & 31) << 2;
            const int cr = tid >> 5;
            #pragma unroll
            for (int r = 0; r < 4; r++) {
                int cc = cr + r * 8;
                *(float4*)&qs[cc * 128 + fc] =
                    *(const float4*)&q[qbase + (long)(c0 + cc) * Tt * NFf + f0 + fc];
            }
            const int nc  = (tid & 15) << 2;
            const int cr2 = tid >> 4;
            #pragma unroll
            for (int r = 0; r < 2; r++) {
                int cc = cr2 + r * 16;
                *(float4*)&ks[cc * 64 + nc] =
                    *(const float4*)&k[kbase + (long)(c0 + cc) * Tt * NBn + nc];
            }
        }
        __syncthreads();
        #pragma unroll 8
        for (int cc = 0; cc < 32; cc++) {
            float4 a0 = *(float4*)&qs[cc * 128 + ty * 8];
            float4 a1 = *(float4*)&qs[cc * 128 + ty * 8 + 4];
            float4 b4 = *(float4*)&ks[cc * 64 + tx * 4];
            float av[8] = {a0.x, a0.y, a0.z, a0.w, a1.x, a1.y, a1.z, a1.w};
            float bv[4] = {b4.x, b4.y, b4.z, b4.w};
            #pragma unroll
            for (int i = 0; i < 8; i++)
                #pragma unroll
                for (int j = 0; j < 4; j++)
                    s[i][j] += av[i] * bv[j];
        }
        __syncthreads();
    }

    #pragma unroll
    for (int i = 0; i < 8; i++) {
        const int f = f0 + ty * 8 + i;
        float mx = -1e30f;
        #pragma unroll
        for (int j = 0; j < 4; j++) {
            s[i][j] = s[i][j] * ss + eb[(tx * 4 + j) * NFf + f] * ps;
            mx = fmaxf(mx, s[i][j]);
        }
        #pragma unroll
        for (int o = 8; o > 0; o >>= 1)
            mx = fmaxf(mx, __shfl_xor_sync(0xffffffffu, mx, o, 16));
        float sum = 0.0f;
        #pragma unroll
        for (int j = 0; j < 4; j++) { float e = expf(s[i][j] - mx); s[i][j] = e; sum += e; }
        #pragma unroll
        for (int o = 8; o > 0; o >>= 1)
            sum += __shfl_xor_sync(0xffffffffu, sum, o, 16);
        float inv = 1.0f / sum;
        #pragma unroll
        for (int j = 0; j < 4; j++) s[i][j] *= inv;
    }

    #pragma unroll
    for (int i = 0; i < 8; i++)
        #pragma unroll
        for (int j = 0; j < 4; j++)
            wst[(tx * 4 + j) * 128 + ty * 8 + i] = s[i][j];

    const int fx = tid & 15, cg = tid >> 4;
    for (int c0 = 0; c0 < Cc; c0 += 32) {
        {
            const int nc = (tid & 15) << 2;
            const int cr = tid >> 4;
            #pragma unroll
            for (int r = 0; r < 2; r++) {
                int cc = cr + r * 16;
                float4 vv4 = *(const float4*)&v[kbase + (long)(c0 + cc) * Tt * NBn + nc];
                vs[(nc + 0) * 36 + cc] = vv4.x;
                vs[(nc + 1) * 36 + cc] = vv4.y;
                vs[(nc + 2) * 36 + cc] = vv4.z;
                vs[(nc + 3) * 36 + cc] = vv4.w;
            }
        }
        __syncthreads();
        float a0[8], a1[8];
        #pragma unroll
        for (int jj = 0; jj < 8; jj++) { a0[jj] = 0.0f; a1[jj] = 0.0f; }
        #pragma unroll 16
        for (int n = 0; n < 64; n++) {
            float4 wa = *(float4*)&wst[n * 128 + fx * 8];
            float4 wb = *(float4*)&wst[n * 128 + fx * 8 + 4];
            float2 vv = *(float2*)&vs[n * 36 + cg * 2];
            float w8[8] = {wa.x, wa.y, wa.z, wa.w, wb.x, wb.y, wb.z, wb.w};
            #pragma unroll
            for (int jj = 0; jj < 8; jj++) {
                a0[jj] += vv.x * w8[jj];
                a1[jj] += vv.y * w8[jj];
            }
        }
        int c = c0 + cg * 2;
        long o0 = qbase + (long)c * Tt * NFf + f0 + fx * 8;
        long o1 = o0 + (long)Tt * NFf;
        *(float4*)&att[o0]     = make_float4(a0[0], a0[1], a0[2], a0[3]);
        *(float4*)&att[o0 + 4] = make_float4(a0[4], a0[5], a0[6], a0[7]);
        *(float4*)&att[o1]     = make_float4(a1[0], a1[1], a1[2], a1[3]);
        *(float4*)&att[o1 + 4] = make_float4(a1[4], a1[5], a1[6], a1[7]);
        __syncthreads();
    }
}

// ---------------- launch ----------------
#define GEMM_SMEM 65536
extern "C" void kernel_launch(void* const* d_in, const int* in_sizes, int n_in,
                              void* d_out, int out_size) {
    (void)in_sizes; (void)n_in; (void)out_size;
    const float* latent = (const float*)d_in[0];
    const float* side   = (const float*)d_in[1];
    const float* eb     = (const float*)d_in[2];
    const float* lp_nw  = (const float*)d_in[3];
    const float* lp_w   = (const float*)d_in[4];
    const float* lp_b   = (const float*)d_in[5];
    const float* qn_w   = (const float*)d_in[6];
    const float* qin_w  = (const float*)d_in[7];
    const float* qin_b  = (const float*)d_in[8];
    const float* qout_w = (const float*)d_in[9];
    const float* qout_b = (const float*)d_in[10];
    const float* q_w    = (const float*)d_in[11];
    const float* q_b    = (const float*)d_in[12];
    const float* k_w    = (const float*)d_in[13];
    const float* k_b    = (const float*)d_in[14];
    const float* v_w    = (const float*)d_in[15];
    const float* v_b    = (const float*)d_in[16];
    const float* o_w    = (const float*)d_in[17];
    const float* o_b    = (const float*)d_in[18];
    const float* ffn_nw = (const float*)d_in[19];
    const float* fin_w  = (const float*)d_in[20];
    const float* fin_b  = (const float*)d_in[21];
    const float* fout_w = (const float*)d_in[22];
    const float* fout_b = (const float*)d_in[23];
    const float* ss     = (const float*)d_in[24];
    const float* ps     = (const float*)d_in[25];
    const float* qss    = (const float*)d_in[26];
    float* out = (float*)d_out;

    float* base = nullptr;
    cudaGetSymbolAddress((void**)&base, g_scratch);
    float* p_ln  = base;
    float* p_lh  = base + (size_t)1 * SZ_SMALL;
    float* p_k   = base + (size_t)2 * SZ_SMALL;
    float* p_v   = base + (size_t)3 * SZ_SMALL;
    float* p_A   = base + (size_t)4 * SZ_SMALL;
    float* p_h2  = p_A  + (size_t)1 * SZ_BIG;
    float* p_u   = p_h2 + (size_t)2 * SZ_BIG;
    float* p_qh  = p_u  + (size_t)1 * SZ_BIG;
    float* p_hid = p_qh + (size_t)1 * SZ_BIG;

    cudaFuncSetAttribute(gemm_mma, cudaFuncAttributeMaxDynamicSharedMemorySize, GEMM_SMEM);

    const int NTB = Tt * NBn;   // 8192
    const int NTF = Tt * NFf;   // 65536

    // latent path
    rms_kernel<<<(Bb * Tt * NBn) / 256, 256>>>(latent, lp_nw, p_ln, NBn, Bb * Tt * NBn);
    dim3 gNB(NTB / 128, 2, Bb);
    gemm_mma<<<gNB, 512, GEMM_SMEM>>>(lp_w, p_ln, p_lh, lp_b, nullptr, nullptr, Cc, NTB, 1);
    gemm_mma<<<gNB, 512, GEMM_SMEM>>>(k_w, p_lh, p_k, k_b, nullptr, nullptr, Cc, NTB, 0);
    gemm_mma<<<gNB, 512, GEMM_SMEM>>>(v_w, p_lh, p_v, v_b, nullptr, nullptr, Cc, NTB, 0);

    // query path
    rms_kernel<<<(Bb * Tt * NFf) / 256, 256>>>(side, qn_w, p_A, NFf, Bb * Tt * NFf);
    dim3 gIN(NTF / 128, 4, Bb);
    gemm_mma<<<gIN, 512, GEMM_SMEM>>>(qin_w, p_A, p_h2, qin_b, nullptr, nullptr, 2 * Cc, NTF, 0);
    swiglu_kernel<<<(Bb * Cc * Tt * NFf / 4) / 256, 256>>>(p_h2, p_u);
    dim3 gNF(NTF / 128, 2, Bb);
    gemm_mma<<<gNF, 512, GEMM_SMEM>>>(qout_w, p_u, p_qh, qout_b, nullptr, nullptr, Cc, NTF, 0);
    gemm_mma<<<gNF, 512, GEMM_SMEM>>>(q_w, p_qh, p_A, q_b, nullptr, nullptr, Cc, NTF, 0);

    // attention
    attn_kernel<<<dim3(NFf / 128, Tt, Bb), 256>>>(p_A, p_k, p_v, eb, ss, ps, p_u);

    // output proj + query skip
    gemm_mma<<<gNF, 512, GEMM_SMEM>>>(o_w, p_u, p_hid, o_b, p_qh, qss, Cc, NTF, 0);

    // FFN
    rms_kernel<<<(Bb * Tt * NFf) / 256, 256>>>(p_hid, ffn_nw, p_A, NFf, Bb * Tt * NFf);
    gemm_mma<<<gIN, 512, GEMM_SMEM>>>(fin_w, p_A, p_h2, fin_b, nullptr, nullptr, 2 * Cc, NTF, 0);
    swiglu_kernel<<<(Bb * Cc * Tt * NFf / 4) / 256, 256>>>(p_h2, p_u);
    gemm_mma<<<gNF, 512, GEMM_SMEM>>>(fout_w, p_u, out, fout_b, p_hid, nullptr, Cc, NTF, 0);
}

// round 9
// speedup vs baseline: 2.1549x; 1.0299x over previous
#include <cuda_runtime.h>
#include <cuda_bf16.h>
#include <math.h>
#include <stdint.h>

#define Bb 4
#define Cc 256
#define Tt 128
#define NBn 64
#define NFf 512

#define SZ_SMALL (Bb * Cc * Tt * NBn)
#define SZ_BIG   (Bb * Cc * Tt * NFf)
__device__ float g_scratch[(size_t)4 * SZ_SMALL + (size_t)6 * SZ_BIG];

__device__ __forceinline__ uint32_t smem_u32(const void* p) {
    uint32_t a;
    asm("{ .reg .u64 t; cvta.to.shared.u64 t, %1; cvt.u32.u64 %0, t; }" : "=r"(a) : "l"(p));
    return a;
}
#define SWZ128(x) ((x) ^ (((x) >> 3) & 0x70))

__device__ __forceinline__ void split8(float4 a, float4 b, uint32_t* h, uint32_t* l) {
    __nv_bfloat162 h0 = __floats2bfloat162_rn(a.x, a.y);
    __nv_bfloat162 h1 = __floats2bfloat162_rn(a.z, a.w);
    __nv_bfloat162 h2 = __floats2bfloat162_rn(b.x, b.y);
    __nv_bfloat162 h3 = __floats2bfloat162_rn(b.z, b.w);
    float2 f0 = __bfloat1622float2(h0), f1 = __bfloat1622float2(h1);
    float2 f2 = __bfloat1622float2(h2), f3 = __bfloat1622float2(h3);
    __nv_bfloat162 l0 = __floats2bfloat162_rn(a.x - f0.x, a.y - f0.y);
    __nv_bfloat162 l1 = __floats2bfloat162_rn(a.z - f1.x, a.w - f1.y);
    __nv_bfloat162 l2 = __floats2bfloat162_rn(b.x - f2.x, b.y - f2.y);
    __nv_bfloat162 l3 = __floats2bfloat162_rn(b.z - f3.x, b.w - f3.y);
    h[0] = *(uint32_t*)&h0; h[1] = *(uint32_t*)&h1; h[2] = *(uint32_t*)&h2; h[3] = *(uint32_t*)&h3;
    l[0] = *(uint32_t*)&l0; l[1] = *(uint32_t*)&l1; l[2] = *(uint32_t*)&l2; l[3] = *(uint32_t*)&l3;
}

#define LDM_X4(r0, r1, r2, r3, a) \
    asm volatile("ldmatrix.sync.aligned.m8n8.x4.shared.b16 {%0,%1,%2,%3}, [%4];" \
        : "=r"(r0), "=r"(r1), "=r"(r2), "=r"(r3) : "r"(a))
#define MMA_BF16(c, a, b0, b1) \
    asm volatile("mma.sync.aligned.m16n8k16.row.col.f32.bf16.bf16.f32 " \
        "{%0,%1,%2,%3}, {%4,%5,%6,%7}, {%8,%9}, {%0,%1,%2,%3};" \
        : "+f"((c)[0]), "+f"((c)[1]), "+f"((c)[2]), "+f"((c)[3]) \
        : "r"((a)[0]), "r"((a)[1]), "r"((a)[2]), "r"((a)[3]), "r"(b0), "r"(b1))

// ===== HMMA GEMM: Y[b,m,n] = sum_k W[m,k] X[b,k,n], K=256, bf16-split x3 =====
// 512 thr, tile 128m x 128n, Kc=64, DOUBLE-buffered smem (2x64KB), 1 sync/chunk.
__global__ void __launch_bounds__(512) gemm_mma(
    const float* __restrict__ W, const float* __restrict__ X, float* __restrict__ Y,
    const float* __restrict__ bias, const float* __restrict__ skip,
    const float* __restrict__ sscale_p, int Mout, int N, int act) {
    extern __shared__ char smem[];
    const uint32_t sb = smem_u32(smem);
    const int tid = threadIdx.x, wid = tid >> 5, lane = tid & 31;
    const long bXoff = (long)blockIdx.z * 256 * N;
    const long bYoff = (long)blockIdx.z * Mout * N;
    const int n0 = blockIdx.x * 128;
    const int m0 = blockIdx.y * 128;

    const int ag = tid & 7, ar = tid >> 3;          // A staging: k-grp, row
    const int bkg = wid & 7, bnh = wid >> 3;        // B staging: k-grp, n-half

    float aP[16], bP[16];

    // stage a chunk from regs into buffer tb (split hi/lo)
    auto stage = [&](uint32_t tb) {
        #pragma unroll
        for (int it = 0; it < 2; it++) {
            float4 u0 = make_float4(aP[it*8+0], aP[it*8+1], aP[it*8+2], aP[it*8+3]);
            float4 u1 = make_float4(aP[it*8+4], aP[it*8+5], aP[it*8+6], aP[it*8+7]);
            uint32_t h[4], l[4];
            split8(u0, u1, h, l);
            uint32_t off = SWZ128((uint32_t)((ar + it * 64) * 128 + ag * 16));
            asm volatile("st.shared.v4.b32 [%0], {%1,%2,%3,%4};" :: "r"(tb + off), "r"(h[0]), "r"(h[1]), "r"(h[2]), "r"(h[3]) : "memory");
            asm volatile("st.shared.v4.b32 [%0], {%1,%2,%3,%4};" :: "r"(tb + 16384 + off), "r"(l[0]), "r"(l[1]), "r"(l[2]), "r"(l[3]) : "memory");
        }
        #pragma unroll
        for (int it = 0; it < 2; it++) {
            int n = lane + bnh * 32 + it * 64;
            float4 u0 = make_float4(bP[it*8+0], bP[it*8+1], bP[it*8+2], bP[it*8+3]);
            float4 u1 = make_float4(bP[it*8+4], bP[it*8+5], bP[it*8+6], bP[it*8+7]);
            uint32_t h[4], l[4];
            split8(u0, u1, h, l);
            uint32_t off = SWZ128((uint32_t)(n * 128 + bkg * 16));
            asm volatile("st.shared.v4.b32 [%0], {%1,%2,%3,%4};" :: "r"(tb + 32768 + off), "r"(h[0]), "r"(h[1]), "r"(h[2]), "r"(h[3]) : "memory");
            asm volatile("st.shared.v4.b32 [%0], {%1,%2,%3,%4};" :: "r"(tb + 49152 + off), "r"(l[0]), "r"(l[1]), "r"(l[2]), "r"(l[3]) : "memory");
        }
    };
    auto gload = [&](int ch) {
        #pragma unroll
        for (int it = 0; it < 2; it++) {
            const float* s = W + (long)(m0 + ar + it * 64) * 256 + ch * 64 + ag * 8;
            float4 u0 = *(const float4*)s, u1 = *(const float4*)(s + 4);
            aP[it*8+0]=u0.x; aP[it*8+1]=u0.y; aP[it*8+2]=u0.z; aP[it*8+3]=u0.w;
            aP[it*8+4]=u1.x; aP[it*8+5]=u1.y; aP[it*8+6]=u1.z; aP[it*8+7]=u1.w;
        }
        #pragma unroll
        for (int it = 0; it < 2; it++) {
            int n = lane + bnh * 32 + it * 64;
            const float* s = X + bXoff + (long)(ch * 64 + bkg * 8) * N + n0 + n;
            #pragma unroll
            for (int j = 0; j < 8; j++) bP[it*8+j] = s[(long)j * N];
        }
    };

    const int wm = wid & 3, wn = wid >> 2;
    float acc[2][4][4];
    #pragma unroll
    for (int mi = 0; mi < 2; mi++)
        #pragma unroll
        for (int ni = 0; ni < 4; ni++)
            #pragma unroll
            for (int r = 0; r < 4; r++) acc[mi][ni][r] = 0.0f;

    uint32_t aRow[2], aMask[2];
    #pragma unroll
    for (int mi = 0; mi < 2; mi++) {
        uint32_t row = wm * 32 + mi * 16 + (lane & 15);
        aRow[mi] = row * 128; aMask[mi] = (aRow[mi] >> 3) & 0x70;
    }
    const uint32_t aKH = (lane >> 4) * 16;
    uint32_t bRow[2], bMask[2];
    #pragma unroll
    for (int pr = 0; pr < 2; pr++) {
        uint32_t nr = wn * 32 + pr * 16 + (lane >> 4) * 8 + (lane & 7);
        bRow[pr] = nr * 128; bMask[pr] = (bRow[pr] >> 3) & 0x70;
    }
    const uint32_t bKH = ((lane >> 3) & 1) * 16;

    // prologue: chunk 0 into buffer 0
    gload(0);
    stage(sb);
    __syncthreads();

    for (int ch = 0; ch < 4; ch++) {
        // issue next-chunk global loads first (latency hides under MMAs)
        if (ch < 3) gload(ch + 1);
        // compute from buffer ch&1
        const uint32_t cb = sb + (uint32_t)(ch & 1) * 65536u;
        const uint32_t aoff[3] = {0u, 0u, 16384u};
        const uint32_t boff[3] = {32768u, 49152u, 32768u};
        #pragma unroll
        for (int p = 0; p < 3; p++) {
            const uint32_t Ab = cb + aoff[p], Bbs = cb + boff[p];
            #pragma unroll
            for (int kk = 0; kk < 4; kk++) {
                uint32_t af[2][4], bf[4][2];
                #pragma unroll
                for (int mi = 0; mi < 2; mi++) {
                    uint32_t addr = Ab + aRow[mi] + (((uint32_t)(kk * 32) + aKH) ^ aMask[mi]);
                    LDM_X4(af[mi][0], af[mi][1], af[mi][2], af[mi][3], addr);
                }
                #pragma unroll
                for (int pr = 0; pr < 2; pr++) {
                    uint32_t addr = Bbs + bRow[pr] + (((uint32_t)(kk * 32) + bKH) ^ bMask[pr]);
                    LDM_X4(bf[pr*2][0], bf[pr*2][1], bf[pr*2+1][0], bf[pr*2+1][1], addr);
                }
                #pragma unroll
                for (int mi = 0; mi < 2; mi++)
                    #pragma unroll
                    for (int ni = 0; ni < 4; ni++)
                        MMA_BF16(acc[mi][ni], af[mi], bf[ni][0], bf[ni][1]);
            }
        }
        // stage next chunk into the other buffer (overlaps other warps' MMAs)
        if (ch < 3) stage(sb + (uint32_t)((ch + 1) & 1) * 65536u);
        __syncthreads();
    }

    // epilogue
    const int gid = lane >> 2, tig = lane & 3;
    const float sc = sscale_p ? *sscale_p : 1.0f;
    #pragma unroll
    for (int mi = 0; mi < 2; mi++) {
        #pragma unroll
        for (int ni = 0; ni < 4; ni++) {
            int m1 = m0 + wm * 32 + mi * 16 + gid;
            int n  = n0 + wn * 32 + ni * 8 + tig * 2;
            float v0 = acc[mi][ni][0] + bias[m1];
            float v1 = acc[mi][ni][1] + bias[m1];
            float v2 = acc[mi][ni][2] + bias[m1 + 8];
            float v3 = acc[mi][ni][3] + bias[m1 + 8];
            if (act) {
                v0 = v0 / (1.0f + expf(-v0)); v1 = v1 / (1.0f + expf(-v1));
                v2 = v2 / (1.0f + expf(-v2)); v3 = v3 / (1.0f + expf(-v3));
            }
            long o1 = bYoff + (long)m1 * N + n;
            long o2 = o1 + (long)8 * N;
            if (skip) {
                float2 s1 = *(const float2*)&skip[o1];
                float2 s2 = *(const float2*)&skip[o2];
                v0 += sc * s1.x; v1 += sc * s1.y; v2 += sc * s2.x; v3 += sc * s2.y;
            }
            *(float2*)&Y[o1] = make_float2(v0, v1);
            *(float2*)&Y[o2] = make_float2(v2, v3);
        }
    }
}

// ---------------- RMSNorm (unchanged, passing) ----------------
__global__ void rms_kernel(const float* __restrict__ x, const float* __restrict__ w,
                           float* __restrict__ y, int Wd, int total) {
    int idx = blockIdx.x * blockDim.x + threadIdx.x;
    if (idx >= total) return;
    int wcol = idx % Wd;
    int bt   = idx / Wd;
    int b = bt / Tt, t = bt % Tt;
    long base   = (long)b * Cc * Tt * Wd + (long)t * Wd + wcol;
    long stride = (long)Tt * Wd;
    float sum = 0.0f;
    #pragma unroll 8
    for (int c = 0; c < Cc; c++) {
        float v = x[base + (long)c * stride];
        sum += v * v;
    }
    float sc = rsqrtf(sum * (1.0f / Cc) + 1e-6f);
    #pragma unroll 8
    for (int c = 0; c < Cc; c++)
        y[base + (long)c * stride] = x[base + (long)c * stride] * sc * w[c];
}

// ---------------- SwiGLU (unchanged, passing) ----------------
__global__ void swiglu_kernel(const float* __restrict__ h2, float* __restrict__ u) {
    const int QUARTER = Cc * Tt * NFf / 4;
    long i = (long)blockIdx.x * blockDim.x + threadIdx.x;
    int bq = (int)(i / QUARTER);
    int r  = (int)(i % QUARTER);
    long a_idx = (long)bq * (2 * QUARTER) + r;
    float4 a = ((const float4*)h2)[a_idx];
    float4 g = ((const float4*)h2)[a_idx + QUARTER];
    float4 o;
    o.x = a.x * (g.x / (1.0f + expf(-g.x)));
    o.y = a.y * (g.y / (1.0f + expf(-g.y)));
    o.z = a.z * (g.z / (1.0f + expf(-g.z)));
    o.w = a.w * (g.w / (1.0f + expf(-g.w)));
    ((float4*)u)[i] = o;
}

// ---------------- fused attention (unchanged, passing) ----------------
__global__ void __launch_bounds__(256) attn_kernel(
    const float* __restrict__ q, const float* __restrict__ k, const float* __restrict__ v,
    const float* __restrict__ eb, const float* __restrict__ ssp, const float* __restrict__ psp,
    float* __restrict__ att) {
    __shared__ float sm[64 * 128 + 64 * 36];
    float* wst = sm;
    float* vs  = sm + 64 * 128;
    float* qs  = sm;
    float* ks  = sm + 32 * 128;

    const int f0 = blockIdx.x * 128;
    const int t  = blockIdx.y;
    const int b  = blockIdx.z;
    const int tid = threadIdx.x;
    const long qbase = (long)b * Cc * Tt * NFf + (long)t * NFf;
    const long kbase = (long)b * Cc * Tt * NBn + (long)t * NBn;
    const float ss = *ssp, ps = *psp;
    const int tx = tid & 15, ty = tid >> 4;

    float s[8][4];
    #pragma unroll
    for (int i = 0; i < 8; i++)
        #pragma unroll
        for (int j = 0; j < 4; j++) s[i][j] = 0.0f;

    for (int c0 = 0; c0 < Cc; c0 += 32) {
        {
            const int fc = (tid & 31) << 2;
            const int cr = tid >> 5;
            #pragma unroll
            for (int r = 0; r < 4; r++) {
                int cc = cr + r * 8;
                *(float4*)&qs[cc * 128 + fc] =
                    *(const float4*)&q[qbase + (long)(c0 + cc) * Tt * NFf + f0 + fc];
            }
            const int nc  = (tid & 15) << 2;
            const int cr2 = tid >> 4;
            #pragma unroll
            for (int r = 0; r < 2; r++) {
                int cc = cr2 + r * 16;
                *(float4*)&ks[cc * 64 + nc] =
                    *(const float4*)&k[kbase + (long)(c0 + cc) * Tt * NBn + nc];
            }
        }
        __syncthreads();
        #pragma unroll 8
        for (int cc = 0; cc < 32; cc++) {
            float4 a0 = *(float4*)&qs[cc * 128 + ty * 8];
            float4 a1 = *(float4*)&qs[cc * 128 + ty * 8 + 4];
            float4 b4 = *(float4*)&ks[cc * 64 + tx * 4];
            float av[8] = {a0.x, a0.y, a0.z, a0.w, a1.x, a1.y, a1.z, a1.w};
            float bv[4] = {b4.x, b4.y, b4.z, b4.w};
            #pragma unroll
            for (int i = 0; i < 8; i++)
                #pragma unroll
                for (int j = 0; j < 4; j++)
                    s[i][j] += av[i] * bv[j];
        }
        __syncthreads();
    }

    #pragma unroll
    for (int i = 0; i < 8; i++) {
        const int f = f0 + ty * 8 + i;
        float mx = -1e30f;
        #pragma unroll
        for (int j = 0; j < 4; j++) {
            s[i][j] = s[i][j] * ss + eb[(tx * 4 + j) * NFf + f] * ps;
            mx = fmaxf(mx, s[i][j]);
        }
        #pragma unroll
        for (int o = 8; o > 0; o >>= 1)
            mx = fmaxf(mx, __shfl_xor_sync(0xffffffffu, mx, o, 16));
        float sum = 0.0f;
        #pragma unroll
        for (int j = 0; j < 4; j++) { float e = expf(s[i][j] - mx); s[i][j] = e; sum += e; }
        #pragma unroll
        for (int o = 8; o > 0; o >>= 1)
            sum += __shfl_xor_sync(0xffffffffu, sum, o, 16);
        float inv = 1.0f / sum;
        #pragma unroll
        for (int j = 0; j < 4; j++) s[i][j] *= inv;
    }

    #pragma unroll
    for (int i = 0; i < 8; i++)
        #pragma unroll
        for (int j = 0; j < 4; j++)
            wst[(tx * 4 + j) * 128 + ty * 8 + i] = s[i][j];

    const int fx = tid & 15, cg = tid >> 4;
    for (int c0 = 0; c0 < Cc; c0 += 32) {
        {
            const int nc = (tid & 15) << 2;
            const int cr = tid >> 4;
            #pragma unroll
            for (int r = 0; r < 2; r++) {
                int cc = cr + r * 16;
                float4 vv4 = *(const float4*)&v[kbase + (long)(c0 + cc) * Tt * NBn + nc];
                vs[(nc + 0) * 36 + cc] = vv4.x;
                vs[(nc + 1) * 36 + cc] = vv4.y;
                vs[(nc + 2) * 36 + cc] = vv4.z;
                vs[(nc + 3) * 36 + cc] = vv4.w;
            }
        }
        __syncthreads();
        float a0[8], a1[8];
        #pragma unroll
        for (int jj = 0; jj < 8; jj++) { a0[jj] = 0.0f; a1[jj] = 0.0f; }
        #pragma unroll 16
        for (int n = 0; n < 64; n++) {
            float4 wa = *(float4*)&wst[n * 128 + fx * 8];
            float4 wb = *(float4*)&wst[n * 128 + fx * 8 + 4];
            float2 vv = *(float2*)&vs[n * 36 + cg * 2];
            float w8[8] = {wa.x, wa.y, wa.z, wa.w, wb.x, wb.y, wb.z, wb.w};
            #pragma unroll
            for (int jj = 0; jj < 8; jj++) {
                a0[jj] += vv.x * w8[jj];
                a1[jj] += vv.y * w8[jj];
            }
        }
        int c = c0 + cg * 2;
        long o0 = qbase + (long)c * Tt * NFf + f0 + fx * 8;
        long o1 = o0 + (long)Tt * NFf;
        *(float4*)&att[o0]     = make_float4(a0[0], a0[1], a0[2], a0[3]);
        *(float4*)&att[o0 + 4] = make_float4(a0[4], a0[5], a0[6], a0[7]);
        *(float4*)&att[o1]     = make_float4(a1[0], a1[1], a1[2], a1[3]);
        *(float4*)&att[o1 + 4] = make_float4(a1[4], a1[5], a1[6], a1[7]);
        __syncthreads();
    }
}

// ---------------- launch ----------------
#define GEMM_SMEM 131072
extern "C" void kernel_launch(void* const* d_in, const int* in_sizes, int n_in,
                              void* d_out, int out_size) {
    (void)in_sizes; (void)n_in; (void)out_size;
    const float* latent = (const float*)d_in[0];
    const float* side   = (const float*)d_in[1];
    const float* eb     = (const float*)d_in[2];
    const float* lp_nw  = (const float*)d_in[3];
    const float* lp_w   = (const float*)d_in[4];
    const float* lp_b   = (const float*)d_in[5];
    const float* qn_w   = (const float*)d_in[6];
    const float* qin_w  = (const float*)d_in[7];
    const float* qin_b  = (const float*)d_in[8];
    const float* qout_w = (const float*)d_in[9];
    const float* qout_b = (const float*)d_in[10];
    const float* q_w    = (const float*)d_in[11];
    const float* q_b    = (const float*)d_in[12];
    const float* k_w    = (const float*)d_in[13];
    const float* k_b    = (const float*)d_in[14];
    const float* v_w    = (const float*)d_in[15];
    const float* v_b    = (const float*)d_in[16];
    const float* o_w    = (const float*)d_in[17];
    const float* o_b    = (const float*)d_in[18];
    const float* ffn_nw = (const float*)d_in[19];
    const float* fin_w  = (const float*)d_in[20];
    const float* fin_b  = (const float*)d_in[21];
    const float* fout_w = (const float*)d_in[22];
    const float* fout_b = (const float*)d_in[23];
    const float* ss     = (const float*)d_in[24];
    const float* ps     = (const float*)d_in[25];
    const float* qss    = (const float*)d_in[26];
    float* out = (float*)d_out;

    float* base = nullptr;
    cudaGetSymbolAddress((void**)&base, g_scratch);
    float* p_ln  = base;
    float* p_lh  = base + (size_t)1 * SZ_SMALL;
    float* p_k   = base + (size_t)2 * SZ_SMALL;
    float* p_v   = base + (size_t)3 * SZ_SMALL;
    float* p_A   = base + (size_t)4 * SZ_SMALL;
    float* p_h2  = p_A  + (size_t)1 * SZ_BIG;
    float* p_u   = p_h2 + (size_t)2 * SZ_BIG;
    float* p_qh  = p_u  + (size_t)1 * SZ_BIG;
    float* p_hid = p_qh + (size_t)1 * SZ_BIG;

    cudaFuncSetAttribute(gemm_mma, cudaFuncAttributeMaxDynamicSharedMemorySize, GEMM_SMEM);

    const int NTB = Tt * NBn;   // 8192
    const int NTF = Tt * NFf;   // 65536

    // latent path
    rms_kernel<<<(Bb * Tt * NBn) / 256, 256>>>(latent, lp_nw, p_ln, NBn, Bb * Tt * NBn);
    dim3 gNB(NTB / 128, 2, Bb);
    gemm_mma<<<gNB, 512, GEMM_SMEM>>>(lp_w, p_ln, p_lh, lp_b, nullptr, nullptr, Cc, NTB, 1);
    gemm_mma<<<gNB, 512, GEMM_SMEM>>>(k_w, p_lh, p_k, k_b, nullptr, nullptr, Cc, NTB, 0);
    gemm_mma<<<gNB, 512, GEMM_SMEM>>>(v_w, p_lh, p_v, v_b, nullptr, nullptr, Cc, NTB, 0);

    // query path
    rms_kernel<<<(Bb * Tt * NFf) / 256, 256>>>(side, qn_w, p_A, NFf, Bb * Tt * NFf);
    dim3 gIN(NTF / 128, 4, Bb);
    gemm_mma<<<gIN, 512, GEMM_SMEM>>>(qin_w, p_A, p_h2, qin_b, nullptr, nullptr, 2 * Cc, NTF, 0);
    swiglu_kernel<<<(Bb * Cc * Tt * NFf / 4) / 256, 256>>>(p_h2, p_u);
    dim3 gNF(NTF / 128, 2, Bb);
    gemm_mma<<<gNF, 512, GEMM_SMEM>>>(qout_w, p_u, p_qh, qout_b, nullptr, nullptr, Cc, NTF, 0);
    gemm_mma<<<gNF, 512, GEMM_SMEM>>>(q_w, p_qh, p_A, q_b, nullptr, nullptr, Cc, NTF, 0);

    // attention
    attn_kernel<<<dim3(NFf / 128, Tt, Bb), 256>>>(p_A, p_k, p_v, eb, ss, ps, p_u);

    // output proj + query skip
    gemm_mma<<<gNF, 512, GEMM_SMEM>>>(o_w, p_u, p_hid, o_b, p_qh, qss, Cc, NTF, 0);

    // FFN
    rms_kernel<<<(Bb * Tt * NFf) / 256, 256>>>(p_hid, ffn_nw, p_A, NFf, Bb * Tt * NFf);
    gemm_mma<<<gIN, 512, GEMM_SMEM>>>(fin_w, p_A, p_h2, fin_b, nullptr, nullptr, 2 * Cc, NTF, 0);
    swiglu_kernel<<<(Bb * Cc * Tt * NFf / 4) / 256, 256>>>(p_h2, p_u);
    gemm_mma<<<gNF, 512, GEMM_SMEM>>>(fout_w, p_u, out, fout_b, p_hid, nullptr, Cc, NTF, 0);
}